// round 14
// baseline (speedup 1.0000x reference)
#include <cuda_runtime.h>
#include <cstddef>

// GRU_AE fused, layer-pipelined, K=8 steps/interval, 2 batches/block, 256
// blocks (2 blocks/SM, single wave). Round-12/13/14:
//  * h-side weights pre-packed in smem as float4 {wc,wc,wc+1,wc+1}; LDS.128 +
//    2 FMA2 per col-pair-gate (eliminates per-use PACK movs on the h chain)
//  * hv and x-side v read as LDS.128 col-pairs
//  * x-side weights in registers (packed once per interval per col)
//  * L3's x-phase offloaded to the FC warp (gx3 parity buffer, L3 delay 3)
//  * role map staggered by block parity; SMSP0 carries the two lightest roles
//    (FC+x3 and L3-h) from both co-resident blocks.
// Schedule (interval m, group g = 8 timesteps):
//  L1: g=m | L2: g=m-1 | x3@FC: g=m-2 | L3: g=m-3 | L4: g=m-4 | FC out: g=m-5
// Writers use slot m&1; readers use slot (m-1)&1. One bar.sync per interval.

#define T_LEN 2048
#define NTHR  160
#define NBLK  256
#define KS    8
#define NINT  261   // 256 groups + 5 drain

#define BAR() asm volatile("bar.sync 0, %0;" :: "n"(NTHR) : "memory")
#define PACK2(d, s)      asm("mov.b64 %0, {%1, %1};" : "=l"(d) : "f"(s))
#define UNPACK2(a, b, s) asm("mov.b64 {%0, %1}, %2;" : "=f"(a), "=f"(b) : "l"(s))
#define FMA2(acc, w, v)  asm("fma.rn.f32x2 %0, %1, %2, %0;" : "+l"(acc) : "l"(w), "l"(v))

typedef unsigned long long u64;

struct Smem {
    float2 xb [2][KS][32];
    float2 hb1[2][KS][32];
    float2 hb2[2][KS][32];
    float2 hb3[2][KS][32];
    float2 hb4[2][KS][32];
    float2 gx3[2][3][KS][32];   // x3 gate accums (cross-warp, parity)
    float2 sc1[3][KS][32];      // lane-private x-accum scratch (same-warp)
    float2 sc2[3][KS][32];
    float2 sc4[3][KS][32];
    float4 pwh1[3][15][30];     // packed-pair h-weights [gate][colpair][unit]
    float4 pwh2[3][8][15];
    float4 pwh3[3][15][30];
    float4 pwh4[3][8][16];
};

static __device__ __forceinline__ float sigm(float x) {
    return __fdividef(1.0f, 1.0f + __expf(-x));
}
static __device__ __forceinline__ float tanh_f(float x) {
    float e = __expf(2.0f * x);
    return 1.0f - __fdividef(2.0f, e + 1.0f);
}

// Stage packed-pair h-weights: dst[(g*NP+cp)*HID+u] = {w[u][2cp]x2, w[u][2cp+1]x2}
template <int HID, int NP>
static __device__ void stage_pwh(float4* dst, const float* __restrict__ whh, int tid) {
    for (int i = tid; i < 3 * NP * HID; i += NTHR) {
        int u  = i % HID;
        int cp = (i / HID) % NP;
        int g  = i / (HID * NP);
        int c0 = 2 * cp, c1 = 2 * cp + 1;
        float w0 = whh[(g * HID + u) * HID + c0];
        float w1 = (c1 < HID) ? whh[(g * HID + u) * HID + c1] : 0.0f;
        dst[i] = make_float4(w0, w0, w1, w1);
    }
}

// One GRU combine step: h-side dots (packed-pair LDS.128) + activations.
template <int HID, int NP>
static __device__ __forceinline__ float2 gru_combine(
    const float4* __restrict__ pwh, int hc,
    const float2* __restrict__ hvrow,   // 32-entry row of prev h
    u64 xr, u64 xz, u64 xm, float bn, float2 hp)
{
    u64 ar = xr, az = xz, an;
    PACK2(an, bn);
#pragma unroll
    for (int cp = 0; cp < NP; ++cp) {
        longlong2 hv2 = *(const longlong2*)(hvrow + 2 * cp);
        float4 w4r = pwh[(0 * NP + cp) * HID + hc];
        float4 w4z = pwh[(1 * NP + cp) * HID + hc];
        float4 w4n = pwh[(2 * NP + cp) * HID + hc];
        const u64* r2 = (const u64*)&w4r;
        const u64* z2 = (const u64*)&w4z;
        const u64* n2 = (const u64*)&w4n;
        FMA2(ar, r2[0], (u64)hv2.x); FMA2(ar, r2[1], (u64)hv2.y);
        FMA2(az, z2[0], (u64)hv2.x); FMA2(az, z2[1], (u64)hv2.y);
        FMA2(an, n2[0], (u64)hv2.x); FMA2(an, n2[1], (u64)hv2.y);
    }
    float arx, ary, azx, azy, anx, any_, mx, my;
    UNPACK2(arx, ary, ar);
    UNPACK2(azx, azy, az);
    UNPACK2(anx, any_, an);
    UNPACK2(mx, my, xm);
    float rx = sigm(arx), ry = sigm(ary);
    float zx = sigm(azx), zy = sigm(azy);
    float nx = tanh_f(fmaf(rx, anx, mx));
    float ny = tanh_f(fmaf(ry, any_, my));
    float2 hn;
    hn.x = nx + zx * (hp.x - nx);
    hn.y = ny + zy * (hp.y - ny);
    return hn;
}

// Self-contained layer: x-phase (register weights, pair loads) -> scratch ->
// serial h-phase. IN must be even.
template <int IN, int HID, int NP, int D>
static __device__ void role_self(
    const float* __restrict__ wih,
    const float* __restrict__ bih, const float* __restrict__ bhh,
    const float4* __restrict__ pwh,
    const float2* __restrict__ vb,   // [2][KS][32] flattened
    float2* hb,                      // [2][KS][32] flattened
    float2* sc,                      // [3][KS][32] flattened
    int lane)
{
    const int hc = (lane < HID) ? lane : 0;
    float wxr[IN], wxz[IN], wxn[IN];
#pragma unroll
    for (int c = 0; c < IN; ++c) {
        wxr[c] = __ldg(wih + (0 * HID + hc) * IN + c);
        wxz[c] = __ldg(wih + (1 * HID + hc) * IN + c);
        wxn[c] = __ldg(wih + (2 * HID + hc) * IN + c);
    }
    const float br = __ldg(bih + hc)           + __ldg(bhh + hc);
    const float bz = __ldg(bih + HID + hc)     + __ldg(bhh + HID + hc);
    const float bm = __ldg(bih + 2 * HID + hc);
    const float bn = __ldg(bhh + 2 * HID + hc);
    u64 pbr, pbz, pbm;
    PACK2(pbr, br); PACK2(pbz, bz); PACK2(pbm, bm);

    float2 hp = {0.f, 0.f};

    for (int m = 0; m < NINT; ++m) {
        if (m >= D && m < D + T_LEN / KS) {
            const int wp = m & 1, rp = wp ^ 1;
            // ---- x-phase: 8 independent steps, col-pair loads ----
            u64 axr[KS], axz[KS], axn[KS];
#pragma unroll
            for (int j = 0; j < KS; ++j) { axr[j] = pbr; axz[j] = pbz; axn[j] = pbm; }
#pragma unroll
            for (int cp = 0; cp < IN / 2; ++cp) {
                const int c = 2 * cp;
                u64 wr0, wr1, wz0, wz1, wn0, wn1;
                PACK2(wr0, wxr[c]); PACK2(wr1, wxr[c + 1]);
                PACK2(wz0, wxz[c]); PACK2(wz1, wxz[c + 1]);
                PACK2(wn0, wxn[c]); PACK2(wn1, wxn[c + 1]);
#pragma unroll
                for (int j = 0; j < KS; ++j) {
                    longlong2 v2 = *(const longlong2*)(vb + (rp * KS + j) * 32 + c);
                    FMA2(axr[j], wr0, (u64)v2.x); FMA2(axr[j], wr1, (u64)v2.y);
                    FMA2(axz[j], wz0, (u64)v2.x); FMA2(axz[j], wz1, (u64)v2.y);
                    FMA2(axn[j], wn0, (u64)v2.x); FMA2(axn[j], wn1, (u64)v2.y);
                }
            }
#pragma unroll
            for (int j = 0; j < KS; ++j) {
                *(u64*)(sc + (0 * KS + j) * 32 + lane) = axr[j];
                *(u64*)(sc + (1 * KS + j) * 32 + lane) = axz[j];
                *(u64*)(sc + (2 * KS + j) * 32 + lane) = axn[j];
            }
            // ---- h-phase: serial over the 8 steps (rolled) ----
#pragma unroll 1
            for (int j = 0; j < KS; ++j) {
                u64 xr = *(const u64*)(sc + (0 * KS + j) * 32 + lane);
                u64 xz = *(const u64*)(sc + (1 * KS + j) * 32 + lane);
                u64 xm = *(const u64*)(sc + (2 * KS + j) * 32 + lane);
                const float2* hv = hb + ((j == 0) ? (rp * KS + KS - 1)
                                                  : (wp * KS + j - 1)) * 32;
                float2 hn = gru_combine<HID, NP>(pwh, hc, hv, xr, xz, xm, bn, hp);
                hp = hn;
                if (lane < HID) hb[(wp * KS + j) * 32 + lane] = hn;
                __syncwarp();
            }
        }
        BAR();
    }
}

// h-only layer (L3): x accums come from gx3 (written by the FC warp).
template <int HID, int NP, int D>
static __device__ void role_h(
    const float4* __restrict__ pwh, const float* __restrict__ bhh,
    const float2* __restrict__ gx,   // [2][3][KS][32] flattened
    float2* hb, int lane)
{
    const int hc = (lane < HID) ? lane : 0;
    const float bn = __ldg(bhh + 2 * HID + hc);
    float2 hp = {0.f, 0.f};

    for (int m = 0; m < NINT; ++m) {
        if (m >= D && m < D + T_LEN / KS) {
            const int wp = m & 1, rp = wp ^ 1;
#pragma unroll 1
            for (int j = 0; j < KS; ++j) {
                u64 xr = *(const u64*)(gx + ((rp * 3 + 0) * KS + j) * 32 + lane);
                u64 xz = *(const u64*)(gx + ((rp * 3 + 1) * KS + j) * 32 + lane);
                u64 xm = *(const u64*)(gx + ((rp * 3 + 2) * KS + j) * 32 + lane);
                const float2* hv = hb + ((j == 0) ? (rp * KS + KS - 1)
                                                  : (wp * KS + j - 1)) * 32;
                float2 hn = gru_combine<HID, NP>(pwh, hc, hv, xr, xz, xm, bn, hp);
                hp = hn;
                if (lane < HID) hb[(wp * KS + j) * 32 + lane] = hn;
                __syncwarp();
            }
        }
        BAR();
    }
}

// FC warp: x loader (group m+1) + x3-phase (group m-2 -> gx3) + FC (group m-5).
static __device__ void role_fcx3(
    const float* __restrict__ wih3,
    const float* __restrict__ bih3, const float* __restrict__ bhh3,
    const float* __restrict__ fcw,  const float* __restrict__ fcb,
    const float* __restrict__ x,    float* __restrict__ out,
    int bbase, int lane,
    const float2* __restrict__ hb2, const float2* __restrict__ hb4,
    float2* gx3, float2* xbuf)
{
    const int hc30 = (lane < 30) ? lane : 0;
    float wxr[15], wxz[15], wxn[15];
#pragma unroll
    for (int c = 0; c < 15; ++c) {
        wxr[c] = __ldg(wih3 + (0 * 30 + hc30) * 15 + c);
        wxz[c] = __ldg(wih3 + (1 * 30 + hc30) * 15 + c);
        wxn[c] = __ldg(wih3 + (2 * 30 + hc30) * 15 + c);
    }
    const float br = __ldg(bih3 + hc30)      + __ldg(bhh3 + hc30);
    const float bz = __ldg(bih3 + 30 + hc30) + __ldg(bhh3 + 30 + hc30);
    const float bm = __ldg(bih3 + 60 + hc30);
    u64 pbr, pbz, pbm;
    PACK2(pbr, br); PACK2(pbz, bz); PACK2(pbm, bm);

    const int c10 = (lane < 10) ? lane : 0;
    float wfc[16];
#pragma unroll
    for (int c = 0; c < 16; ++c) wfc[c] = __ldg(fcw + c10 * 16 + c);
    const float bfc = __ldg(fcb + c10);
    u64 pbfc; PACK2(pbfc, bfc);

    for (int m = 0; m < NINT; ++m) {
        const int wp = m & 1, rp = wp ^ 1;

        // -- loader: LDG x group m+1 early (latency hidden by x3/FC work) --
        float2 xv[KS];
        const bool ldx = (m + 1 < T_LEN / KS);
        if (ldx) {
#pragma unroll
            for (int j = 0; j < KS; ++j) {
                size_t off = (size_t)(KS * (m + 1) + j) * 32 + lane;
                xv[j].x = __ldg(x + (size_t)(bbase + 0) * T_LEN * 32 + off);
                xv[j].y = __ldg(x + (size_t)(bbase + 1) * T_LEN * 32 + off);
            }
        }

        // -- x3-phase: group m-2 from hb2 (written at m-1) --
        if (m >= 2 && m < 2 + T_LEN / KS) {
            u64 axr[KS], axz[KS], axn[KS];
#pragma unroll
            for (int j = 0; j < KS; ++j) { axr[j] = pbr; axz[j] = pbz; axn[j] = pbm; }
#pragma unroll
            for (int cp = 0; cp < 7; ++cp) {
                const int c = 2 * cp;
                u64 wr0, wr1, wz0, wz1, wn0, wn1;
                PACK2(wr0, wxr[c]); PACK2(wr1, wxr[c + 1]);
                PACK2(wz0, wxz[c]); PACK2(wz1, wxz[c + 1]);
                PACK2(wn0, wxn[c]); PACK2(wn1, wxn[c + 1]);
#pragma unroll
                for (int j = 0; j < KS; ++j) {
                    longlong2 v2 = *(const longlong2*)(hb2 + (rp * KS + j) * 32 + c);
                    FMA2(axr[j], wr0, (u64)v2.x); FMA2(axr[j], wr1, (u64)v2.y);
                    FMA2(axz[j], wz0, (u64)v2.x); FMA2(axz[j], wz1, (u64)v2.y);
                    FMA2(axn[j], wn0, (u64)v2.x); FMA2(axn[j], wn1, (u64)v2.y);
                }
            }
            {   // tail col 14
                u64 wr0, wz0, wn0;
                PACK2(wr0, wxr[14]); PACK2(wz0, wxz[14]); PACK2(wn0, wxn[14]);
#pragma unroll
                for (int j = 0; j < KS; ++j) {
                    u64 v2 = *(const u64*)(hb2 + (rp * KS + j) * 32 + 14);
                    FMA2(axr[j], wr0, v2);
                    FMA2(axz[j], wz0, v2);
                    FMA2(axn[j], wn0, v2);
                }
            }
#pragma unroll
            for (int j = 0; j < KS; ++j) {
                *(u64*)(gx3 + ((wp * 3 + 0) * KS + j) * 32 + lane) = axr[j];
                *(u64*)(gx3 + ((wp * 3 + 1) * KS + j) * 32 + lane) = axz[j];
                *(u64*)(gx3 + ((wp * 3 + 2) * KS + j) * 32 + lane) = axn[j];
            }
        }

        // -- FC: group m-5 from hb4 (written at m-1) --
        if (m >= 5 && m < 5 + T_LEN / KS) {
            u64 acc[KS];
#pragma unroll
            for (int j = 0; j < KS; ++j) acc[j] = pbfc;
#pragma unroll
            for (int c = 0; c < 16; ++c) {
                u64 wp2; PACK2(wp2, wfc[c]);
#pragma unroll
                for (int j = 0; j < KS; ++j) {
                    u64 v2 = *(const u64*)(hb4 + (rp * KS + j) * 32 + c);
                    FMA2(acc[j], wp2, v2);
                }
            }
            if (lane < 10) {
                const int g = m - 5;
#pragma unroll
                for (int j = 0; j < KS; ++j) {
                    float a0, a1;
                    UNPACK2(a0, a1, acc[j]);
                    size_t base = ((size_t)bbase * 10 + lane) * T_LEN + (KS * g + j);
                    out[base]                      = a0;
                    out[base + 10 * (size_t)T_LEN] = a1;
                }
            }
        }

        // -- publish x group m+1 --
        if (ldx) {
#pragma unroll
            for (int j = 0; j < KS; ++j)
                xbuf[(wp * KS + j) * 32 + lane] = xv[j];
        }
        BAR();
    }
}

__global__ void __launch_bounds__(NTHR, 2)
gru_ae_k8c_kernel(const float* __restrict__ x,
                  const float* __restrict__ fcw,  const float* __restrict__ fcb,
                  const float* __restrict__ wih1, const float* __restrict__ whh1,
                  const float* __restrict__ bih1, const float* __restrict__ bhh1,
                  const float* __restrict__ wih2, const float* __restrict__ whh2,
                  const float* __restrict__ bih2, const float* __restrict__ bhh2,
                  const float* __restrict__ wih3, const float* __restrict__ whh3,
                  const float* __restrict__ bih3, const float* __restrict__ bhh3,
                  const float* __restrict__ wih4, const float* __restrict__ whh4,
                  const float* __restrict__ bih4, const float* __restrict__ bhh4,
                  float* __restrict__ out)
{
    extern __shared__ char raw[];
    Smem* sm = (Smem*)raw;

    const int tid   = threadIdx.x;
    const int wid   = tid >> 5;
    const int lane  = tid & 31;
    const int bbase = blockIdx.x * 2;
    const bool odd  = (blockIdx.x & 1) != 0;

    stage_pwh<30, 15>(&sm->pwh1[0][0][0], whh1, tid);
    stage_pwh<15, 8 >(&sm->pwh2[0][0][0], whh2, tid);
    stage_pwh<30, 15>(&sm->pwh3[0][0][0], whh3, tid);
    stage_pwh<16, 8 >(&sm->pwh4[0][0][0], whh4, tid);
    {
        float2 z2 = {0.f, 0.f};
        float2* zb = &sm->xb[0][0][0];
        // xb + hb1..hb4 + gx3 are contiguous: 5*512 + 1536 = 4096 float2
        for (int i = tid; i < 4096; i += NTHR) zb[i] = z2;
    }
    __syncthreads();

    // Prelude: x group 0 into xb slot 1 (L1 at m=0 reads slot (0-1)&1 = 1).
    if (wid == 0) {
#pragma unroll
        for (int j = 0; j < KS; ++j) {
            size_t off = (size_t)j * 32 + lane;
            float2 xv;
            xv.x = __ldg(x + (size_t)(bbase + 0) * T_LEN * 32 + off);
            xv.y = __ldg(x + (size_t)(bbase + 1) * T_LEN * 32 + off);
            sm->xb[1][j][lane] = xv;
        }
    }
    __syncthreads();

    // Roles: 0=L1 1=L2 2=L3 3=L4 4=FCX3.
    // even block: wid {0,1,2,3,4} -> {4,0,1,3,2}
    // odd  block: wid {0,1,2,3,4} -> {2,1,0,3,4}
    // => SMSP0 carries {FCX3,L3} from both blocks (4 lightest warp-instances);
    //    SMSP1/2 carry {L1,L2} cross-paired; SMSP3 carries {L4,L4}.
    int role;
    if (!odd) role = (wid == 0) ? 4 : (wid == 1) ? 0 : (wid == 2) ? 1 : (wid == 3) ? 3 : 2;
    else      role = (wid == 0) ? 2 : (wid == 1) ? 1 : (wid == 2) ? 0 : (wid == 3) ? 3 : 4;

    if (role == 0) {
        role_self<32, 30, 15, 0>(wih1, bih1, bhh1, &sm->pwh1[0][0][0],
                                 &sm->xb[0][0][0], &sm->hb1[0][0][0],
                                 &sm->sc1[0][0][0], lane);
    } else if (role == 1) {
        role_self<30, 15, 8, 1>(wih2, bih2, bhh2, &sm->pwh2[0][0][0],
                                &sm->hb1[0][0][0], &sm->hb2[0][0][0],
                                &sm->sc2[0][0][0], lane);
    } else if (role == 2) {
        role_h<30, 15, 3>(&sm->pwh3[0][0][0], bhh3,
                          &sm->gx3[0][0][0][0], &sm->hb3[0][0][0], lane);
    } else if (role == 3) {
        role_self<30, 16, 8, 4>(wih4, bih4, bhh4, &sm->pwh4[0][0][0],
                                &sm->hb3[0][0][0], &sm->hb4[0][0][0],
                                &sm->sc4[0][0][0], lane);
    } else {
        role_fcx3(wih3, bih3, bhh3, fcw, fcb, x, out, bbase, lane,
                  &sm->hb2[0][0][0], &sm->hb4[0][0][0],
                  &sm->gx3[0][0][0][0], &sm->xb[0][0][0]);
    }
}

extern "C" void kernel_launch(void* const* d_in, const int* in_sizes, int n_in,
                              void* d_out, int out_size) {
    (void)in_sizes; (void)n_in; (void)out_size;
    const float* x    = (const float*)d_in[0];
    const float* fcw  = (const float*)d_in[1];
    const float* fcb  = (const float*)d_in[2];
    const float* wih1 = (const float*)d_in[3];
    const float* whh1 = (const float*)d_in[4];
    const float* bih1 = (const float*)d_in[5];
    const float* bhh1 = (const float*)d_in[6];
    const float* wih2 = (const float*)d_in[7];
    const float* whh2 = (const float*)d_in[8];
    const float* bih2 = (const float*)d_in[9];
    const float* bhh2 = (const float*)d_in[10];
    const float* wih3 = (const float*)d_in[11];
    const float* whh3 = (const float*)d_in[12];
    const float* bih3 = (const float*)d_in[13];
    const float* bhh3 = (const float*)d_in[14];
    const float* wih4 = (const float*)d_in[15];
    const float* whh4 = (const float*)d_in[16];
    const float* bih4 = (const float*)d_in[17];
    const float* bhh4 = (const float*)d_in[18];
    float* out = (float*)d_out;

    cudaFuncSetAttribute(gru_ae_k8c_kernel,
                         cudaFuncAttributeMaxDynamicSharedMemorySize,
                         (int)sizeof(Smem));

    gru_ae_k8c_kernel<<<NBLK, NTHR, sizeof(Smem)>>>(
        x, fcw, fcb,
        wih1, whh1, bih1, bhh1,
        wih2, whh2, bih2, bhh2,
        wih3, whh3, bih3, bhh3,
        wih4, whh4, bih4, bhh4,
        out);
}

// round 15
// speedup vs baseline: 1.2999x; 1.2999x over previous
#include <cuda_runtime.h>
#include <cstddef>

// GRU_AE fused, layer-pipelined, K=8 steps/interval, 2 batches/block, 256
// blocks (2 blocks/SM, single wave). R10 base + ONE change:
//  L1/L3 (HID=30) h-side weights pre-packed in smem as float4
//  {wc,wc,wc+1,wc+1}; h-phase does LDS.128 + 2 FMA2 per col-pair-gate,
//  eliminating the per-use PACK movs on the serial h chain. L2/L4 keep
//  register h-weights (small, spill-safe). x-side stays R10 (smem scalar
//  weights, PACK once per col per interval, amortized over 8 steps).

#define T_LEN 2048
#define NTHR  160
#define NBLK  256
#define KS    8
#define NINT  (T_LEN / KS + 4)   // 260

#define BAR() asm volatile("bar.sync 0, %0;" :: "n"(NTHR) : "memory")
#define PACK2(d, s)      asm("mov.b64 %0, {%1, %1};" : "=l"(d) : "f"(s))
#define PACK2V(d, s)     asm volatile("mov.b64 %0, {%1, %1};" : "=l"(d) : "f"(s))
#define UNPACK2(a, b, s) asm("mov.b64 {%0, %1}, %2;" : "=f"(a), "=f"(b) : "l"(s))
#define FMA2(acc, w, v)  asm("fma.rn.f32x2 %0, %1, %2, %0;" : "+l"(acc) : "l"(w), "l"(v))

typedef unsigned long long u64;

struct Smem {
    float4 pwh1[3][15][30];     // packed-pair h-weights (L1) [gate][colpair][unit]
    float4 pwh3[3][15][30];     // packed-pair h-weights (L3)
    float2 xb [2][KS][32];
    float2 hb1[2][KS][32];
    float2 hb2[2][KS][32];
    float2 hb3[2][KS][32];
    float2 hb4[2][KS][32];
    float2 g1[3][KS][30];       // x-accum scratch (lane-private, guarded)
    float2 g2[3][KS][16];
    float2 g3[3][KS][30];
    float2 g4[3][KS][16];
    float  wtx1[3][32][30];     // x-side weights, transposed [gate][col][unit]
    float  wtx2[3][30][15];
    float  wtx3[3][15][30];
    float  wtx4[3][30][16];
};

static __device__ __forceinline__ float sigm(float x) {
    return __fdividef(1.0f, 1.0f + __expf(-x));
}
static __device__ __forceinline__ float tanh_f(float x) {
    float e = __expf(2.0f * x);
    return 1.0f - __fdividef(2.0f, e + 1.0f);
}

// Stage x-side weights transposed: dst[(g*IN + c)*HID + u] = wih[(g*HID+u)*IN + c]
template <int IN, int HID>
static __device__ void stage_x(float* dst, const float* __restrict__ wih, int tid) {
    for (int i = tid; i < 3 * IN * HID; i += NTHR) {
        int u = i % HID;
        int gc = i / HID;
        int c = gc % IN;
        int g = gc / IN;
        dst[(g * IN + c) * HID + u] = wih[(g * HID + u) * IN + c];
    }
}

// Stage packed-pair h-weights: dst[(g*NP+cp)*HID+u] = {w[u][2cp]x2, w[u][2cp+1]x2}
template <int HID, int NP>
static __device__ void stage_pwh(float4* dst, const float* __restrict__ whh, int tid) {
    for (int i = tid; i < 3 * NP * HID; i += NTHR) {
        int u  = i % HID;
        int cp = (i / HID) % NP;
        int g  = i / (HID * NP);
        float w0 = whh[(g * HID + u) * HID + 2 * cp];
        float w1 = whh[(g * HID + u) * HID + 2 * cp + 1];
        dst[i] = make_float4(w0, w0, w1, w1);
    }
}

// Shared x-phase: 8 independent steps, smem scalar weights packed per col,
// results into guarded lane-private scratch gx[3][KS][HID].
template <int IN, int HID>
static __device__ __forceinline__ void x_phase(
    const float* __restrict__ wtx, float2* gx,
    const float2* __restrict__ vb, int rp, int hc, bool active,
    u64 pbr, u64 pbz, u64 pbm)
{
    u64 axr[KS], axz[KS], axn[KS];
#pragma unroll
    for (int j = 0; j < KS; ++j) { axr[j] = pbr; axz[j] = pbz; axn[j] = pbm; }
#pragma unroll 4
    for (int c = 0; c < IN; ++c) {
        u64 wrp, wzp, wnp;
        float a = wtx[(0 * IN + c) * HID + hc];
        float b = wtx[(1 * IN + c) * HID + hc];
        float d = wtx[(2 * IN + c) * HID + hc];
        PACK2(wrp, a); PACK2(wzp, b); PACK2(wnp, d);
#pragma unroll
        for (int j = 0; j < KS; ++j) {
            u64 v2 = *(const u64*)(vb + (rp * KS + j) * 32 + c);   // broadcast
            FMA2(axr[j], wrp, v2);
            FMA2(axz[j], wzp, v2);
            FMA2(axn[j], wnp, v2);
        }
    }
    if (active) {
#pragma unroll
        for (int j = 0; j < KS; ++j) {
            *(u64*)(gx + (0 * KS + j) * HID + hc) = axr[j];
            *(u64*)(gx + (1 * KS + j) * HID + hc) = axz[j];
            *(u64*)(gx + (2 * KS + j) * HID + hc) = axn[j];
        }
    }
}

// Heavy layer (HID=30): packed-pair h-weights from smem (no PACK in h chain).
template <int IN, int D>
static __device__ void layer_pwh(
    const float* __restrict__ wtx, const float4* __restrict__ pwh,
    float2* gx,
    const float* __restrict__ bih, const float* __restrict__ bhh,
    const float2* __restrict__ vb, float2* hb, int lane)
{
    const int HID = 30, NP = 15;
    const int hc = (lane < HID) ? lane : 0;
    const bool act_lane = (lane < HID);
    const float br = __ldg(bih + hc)           + __ldg(bhh + hc);
    const float bz = __ldg(bih + HID + hc)     + __ldg(bhh + HID + hc);
    const float bm = __ldg(bih + 2 * HID + hc);
    const float bn = __ldg(bhh + 2 * HID + hc);
    u64 pbr, pbz, pbm, pbn;
    PACK2(pbr, br); PACK2(pbz, bz); PACK2(pbm, bm); PACK2(pbn, bn);

    float2 hp = {0.f, 0.f};

    for (int m = 0; m < NINT; ++m) {
        if (m >= D && m < D + T_LEN / KS) {
            const int wp = m & 1, rp = wp ^ 1;
            x_phase<IN, HID>(wtx, gx, vb, rp, hc, act_lane, pbr, pbz, pbm);
            // ---- h-phase: serial over the 8 steps (rolled) ----
#pragma unroll 1
            for (int j = 0; j < KS; ++j) {
                u64 ar = *(const u64*)(gx + (0 * KS + j) * HID + hc);
                u64 az = *(const u64*)(gx + (1 * KS + j) * HID + hc);
                u64 xm = *(const u64*)(gx + (2 * KS + j) * HID + hc);
                u64 an = pbn;
                const float2* hv = hb + ((j == 0) ? (rp * KS + KS - 1)
                                                  : (wp * KS + j - 1)) * 32;
#pragma unroll
                for (int cp = 0; cp < NP; ++cp) {
                    longlong2 hv2 = *(const longlong2*)(hv + 2 * cp);   // LDS.128
                    float4 w4r = pwh[(0 * NP + cp) * HID + hc];
                    float4 w4z = pwh[(1 * NP + cp) * HID + hc];
                    float4 w4n = pwh[(2 * NP + cp) * HID + hc];
                    const u64* r2 = (const u64*)&w4r;
                    const u64* z2 = (const u64*)&w4z;
                    const u64* n2 = (const u64*)&w4n;
                    FMA2(ar, r2[0], (u64)hv2.x); FMA2(ar, r2[1], (u64)hv2.y);
                    FMA2(az, z2[0], (u64)hv2.x); FMA2(az, z2[1], (u64)hv2.y);
                    FMA2(an, n2[0], (u64)hv2.x); FMA2(an, n2[1], (u64)hv2.y);
                }
                float arx, ary, azx, azy, anx, any_, mx, my;
                UNPACK2(arx, ary, ar);
                UNPACK2(azx, azy, az);
                UNPACK2(anx, any_, an);
                UNPACK2(mx, my, xm);
                float rx = sigm(arx), ry = sigm(ary);
                float zx = sigm(azx), zy = sigm(azy);
                float nx = tanh_f(fmaf(rx, anx, mx));
                float ny = tanh_f(fmaf(ry, any_, my));
                float2 hn;
                hn.x = nx + zx * (hp.x - nx);
                hn.y = ny + zy * (hp.y - ny);
                hp = hn;
                if (act_lane) hb[(wp * KS + j) * 32 + lane] = hn;
                __syncwarp();
            }
        }
        BAR();
    }
}

// Light layer (HID<=16): register h-weights + PACK2V (R10 path, spill-safe).
template <int IN, int HID, int D>
static __device__ void layer_reg(
    const float* __restrict__ wtx, float2* gx,
    const float* __restrict__ whh,
    const float* __restrict__ bih, const float* __restrict__ bhh,
    const float2* __restrict__ vb, float2* hb, int lane)
{
    const int hc = (lane < HID) ? lane : 0;
    const bool act_lane = (lane < HID);
    float wr[HID], wz[HID], wn[HID];
#pragma unroll
    for (int c = 0; c < HID; ++c) {
        wr[c] = __ldg(whh + (0 * HID + hc) * HID + c);
        wz[c] = __ldg(whh + (1 * HID + hc) * HID + c);
        wn[c] = __ldg(whh + (2 * HID + hc) * HID + c);
    }
    const float br = __ldg(bih + hc)           + __ldg(bhh + hc);
    const float bz = __ldg(bih + HID + hc)     + __ldg(bhh + HID + hc);
    const float bm = __ldg(bih + 2 * HID + hc);
    const float bn = __ldg(bhh + 2 * HID + hc);
    u64 pbr, pbz, pbm;
    PACK2(pbr, br); PACK2(pbz, bz); PACK2(pbm, bm);

    float2 hp = {0.f, 0.f};

    for (int m = 0; m < NINT; ++m) {
        if (m >= D && m < D + T_LEN / KS) {
            const int wp = m & 1, rp = wp ^ 1;
            x_phase<IN, HID>(wtx, gx, vb, rp, hc, act_lane, pbr, pbz, pbm);
#pragma unroll 1
            for (int j = 0; j < KS; ++j) {
                u64 ar = *(const u64*)(gx + (0 * KS + j) * HID + hc);
                u64 az = *(const u64*)(gx + (1 * KS + j) * HID + hc);
                u64 xm = *(const u64*)(gx + (2 * KS + j) * HID + hc);
                u64 an; PACK2V(an, bn);
                const float2* hv = hb + ((j == 0) ? (rp * KS + KS - 1)
                                                  : (wp * KS + j - 1)) * 32;
#pragma unroll
                for (int c = 0; c < HID; ++c) {
                    u64 h2 = *(const u64*)(hv + c);
                    u64 t;
                    PACK2V(t, wr[c]); FMA2(ar, t, h2);
                    PACK2V(t, wz[c]); FMA2(az, t, h2);
                    PACK2V(t, wn[c]); FMA2(an, t, h2);
                }
                float arx, ary, azx, azy, anx, any_, mx, my;
                UNPACK2(arx, ary, ar);
                UNPACK2(azx, azy, az);
                UNPACK2(anx, any_, an);
                UNPACK2(mx, my, xm);
                float rx = sigm(arx), ry = sigm(ary);
                float zx = sigm(azx), zy = sigm(azy);
                float nx = tanh_f(fmaf(rx, anx, mx));
                float ny = tanh_f(fmaf(ry, any_, my));
                float2 hn;
                hn.x = nx + zx * (hp.x - nx);
                hn.y = ny + zy * (hp.y - ny);
                hp = hn;
                if (act_lane) hb[(wp * KS + j) * 32 + lane] = hn;
                __syncwarp();
            }
        }
        BAR();
    }
}

// FC warp: FC for group m-4 + x loader for group m+1 (R10 verbatim).
static __device__ void fc_warp(
    const float* __restrict__ fcw, const float* __restrict__ fcb,
    const float* __restrict__ x,   float* __restrict__ out,
    int bbase, int lane,
    const float2* __restrict__ hb4, float2* xb)
{
    const int c10 = (lane < 10) ? lane : 0;
    float w[16];
#pragma unroll
    for (int c = 0; c < 16; ++c) w[c] = __ldg(fcw + c10 * 16 + c);
    const float bfc = __ldg(fcb + c10);

    for (int m = 0; m < NINT; ++m) {
        const int wp = m & 1, rp = wp ^ 1;
#pragma unroll
        for (int j = 0; j < KS; ++j) {
            int s = KS * (m + 1) + j;
            if (s < T_LEN) {
                size_t off = (size_t)s * 32 + lane;
                float2 xv;
                xv.x = __ldg(x + (size_t)(bbase + 0) * T_LEN * 32 + off);
                xv.y = __ldg(x + (size_t)(bbase + 1) * T_LEN * 32 + off);
                xb[(wp * KS + j) * 32 + lane] = xv;
            }
        }
        if (m >= 4) {
#pragma unroll
            for (int j = 0; j < KS; ++j) {
                int t = KS * (m - 4) + j;
                const float2* h4 = hb4 + (rp * KS + j) * 32;
                float2 acc = make_float2(bfc, bfc);
#pragma unroll
                for (int c = 0; c < 16; ++c) {
                    float2 v = h4[c];
                    acc.x = fmaf(w[c], v.x, acc.x);
                    acc.y = fmaf(w[c], v.y, acc.y);
                }
                if (lane < 10) {
                    size_t base = ((size_t)bbase * 10 + lane) * T_LEN + t;
                    out[base]                      = acc.x;
                    out[base + 10 * (size_t)T_LEN] = acc.y;
                }
            }
        }
        BAR();
    }
}

__global__ void __launch_bounds__(NTHR, 2)
gru_ae_k8d_kernel(const float* __restrict__ x,
                  const float* __restrict__ fcw,  const float* __restrict__ fcb,
                  const float* __restrict__ wih1, const float* __restrict__ whh1,
                  const float* __restrict__ bih1, const float* __restrict__ bhh1,
                  const float* __restrict__ wih2, const float* __restrict__ whh2,
                  const float* __restrict__ bih2, const float* __restrict__ bhh2,
                  const float* __restrict__ wih3, const float* __restrict__ whh3,
                  const float* __restrict__ bih3, const float* __restrict__ bhh3,
                  const float* __restrict__ wih4, const float* __restrict__ whh4,
                  const float* __restrict__ bih4, const float* __restrict__ bhh4,
                  float* __restrict__ out)
{
    extern __shared__ char raw[];
    Smem* sm = (Smem*)raw;

    const int tid   = threadIdx.x;
    const int wid   = tid >> 5;
    const int lane  = tid & 31;
    const int bbase = blockIdx.x * 2;
    const bool odd  = (blockIdx.x & 1) != 0;

    stage_x<32, 30>(&sm->wtx1[0][0][0], wih1, tid);
    stage_x<30, 15>(&sm->wtx2[0][0][0], wih2, tid);
    stage_x<15, 30>(&sm->wtx3[0][0][0], wih3, tid);
    stage_x<30, 16>(&sm->wtx4[0][0][0], wih4, tid);
    stage_pwh<30, 15>(&sm->pwh1[0][0][0], whh1, tid);
    stage_pwh<30, 15>(&sm->pwh3[0][0][0], whh3, tid);
    {
        float2 z2 = {0.f, 0.f};
        float2* zb = &sm->xb[0][0][0];     // xb + hb1..hb4 contiguous
        for (int i = tid; i < 5 * 2 * KS * 32; i += NTHR) zb[i] = z2;
    }
    __syncthreads();

    // Prelude: x group 0 into xb slot 1 (L1 at m=0 reads parity 1).
    if (wid == 0) {
#pragma unroll
        for (int j = 0; j < KS; ++j) {
            size_t off = (size_t)j * 32 + lane;
            float2 xv;
            xv.x = __ldg(x + (size_t)(bbase + 0) * T_LEN * 32 + off);
            xv.y = __ldg(x + (size_t)(bbase + 1) * T_LEN * 32 + off);
            sm->xb[1][j][lane] = xv;
        }
    }
    __syncthreads();

    // Parity-staggered layer->warp map (SMSP = wid%4), as R10:
    //  even block: wid0=L2 wid1=L1 wid2=L3 wid3=L4 wid4=FC
    //  odd  block: wid0=L4 wid1=L3 wid2=L2 wid3=L1 wid4=FC
    if (wid == 4) {
        fc_warp(fcw, fcb, x, out, bbase, lane,
                &sm->hb4[0][0][0], &sm->xb[0][0][0]);
    } else if ((!odd && wid == 1) || (odd && wid == 3)) {
        layer_pwh<32, 0>(&sm->wtx1[0][0][0], &sm->pwh1[0][0][0],
                         &sm->g1[0][0][0], bih1, bhh1,
                         &sm->xb[0][0][0], &sm->hb1[0][0][0], lane);
    } else if ((!odd && wid == 0) || (odd && wid == 2)) {
        layer_reg<30, 15, 1>(&sm->wtx2[0][0][0], &sm->g2[0][0][0], whh2,
                             bih2, bhh2,
                             &sm->hb1[0][0][0], &sm->hb2[0][0][0], lane);
    } else if ((!odd && wid == 2) || (odd && wid == 1)) {
        layer_pwh<15, 2>(&sm->wtx3[0][0][0], &sm->pwh3[0][0][0],
                         &sm->g3[0][0][0], bih3, bhh3,
                         &sm->hb2[0][0][0], &sm->hb3[0][0][0], lane);
    } else {
        layer_reg<30, 16, 3>(&sm->wtx4[0][0][0], &sm->g4[0][0][0], whh4,
                             bih4, bhh4,
                             &sm->hb3[0][0][0], &sm->hb4[0][0][0], lane);
    }
}

extern "C" void kernel_launch(void* const* d_in, const int* in_sizes, int n_in,
                              void* d_out, int out_size) {
    (void)in_sizes; (void)n_in; (void)out_size;
    const float* x    = (const float*)d_in[0];
    const float* fcw  = (const float*)d_in[1];
    const float* fcb  = (const float*)d_in[2];
    const float* wih1 = (const float*)d_in[3];
    const float* whh1 = (const float*)d_in[4];
    const float* bih1 = (const float*)d_in[5];
    const float* bhh1 = (const float*)d_in[6];
    const float* wih2 = (const float*)d_in[7];
    const float* whh2 = (const float*)d_in[8];
    const float* bih2 = (const float*)d_in[9];
    const float* bhh2 = (const float*)d_in[10];
    const float* wih3 = (const float*)d_in[11];
    const float* whh3 = (const float*)d_in[12];
    const float* bih3 = (const float*)d_in[13];
    const float* bhh3 = (const float*)d_in[14];
    const float* wih4 = (const float*)d_in[15];
    const float* whh4 = (const float*)d_in[16];
    const float* bih4 = (const float*)d_in[17];
    const float* bhh4 = (const float*)d_in[18];
    float* out = (float*)d_out;

    cudaFuncSetAttribute(gru_ae_k8d_kernel,
                         cudaFuncAttributeMaxDynamicSharedMemorySize,
                         (int)sizeof(Smem));

    gru_ae_k8d_kernel<<<NBLK, NTHR, sizeof(Smem)>>>(
        x, fcw, fcb,
        wih1, whh1, bih1, bhh1,
        wih2, whh2, bih2, bhh2,
        wih3, whh3, bih3, bhh3,
        wih4, whh4, bih4, bhh4,
        out);
}

// round 16
// speedup vs baseline: 1.4439x; 1.1108x over previous
#include <cuda_runtime.h>
#include <cstddef>

// GRU_AE fused, layer-pipelined, K=8 steps/interval, 2 batches/block, 256
// blocks (2 blocks/SM, single wave). R10 base + packed-pair h-weights for the
// HID=30 layers — with NO address-of-local pattern (k8c/k8d demoted the
// float4 weight temp to local memory via (u64*)&w4; this version loads
// longlong2 straight from smem and uses value member access only).
//  L1/L3 h-phase: per col-pair-gate = 1 LDS.128 + 2 FMA2, zero PACK movs.
//  L2/L4 keep register h-weights + PACK2V (R10 path, measured safe).
//  x-side: smem scalar weights, PACK once per col per interval (R10 path).

#define T_LEN 2048
#define NTHR  160
#define NBLK  256
#define KS    8
#define NINT  (T_LEN / KS + 4)   // 260

#define BAR() asm volatile("bar.sync 0, %0;" :: "n"(NTHR) : "memory")
#define PACK2(d, s)      asm("mov.b64 %0, {%1, %1};" : "=l"(d) : "f"(s))
#define PACK2V(d, s)     asm volatile("mov.b64 %0, {%1, %1};" : "=l"(d) : "f"(s))
#define UNPACK2(a, b, s) asm("mov.b64 {%0, %1}, %2;" : "=f"(a), "=f"(b) : "l"(s))
#define FMA2(acc, w, v)  asm("fma.rn.f32x2 %0, %1, %2, %0;" : "+l"(acc) : "l"(w), "l"(v))

typedef unsigned long long u64;

struct Smem {
    float4 pwh1[3][15][30];     // packed-pair h-weights (L1) [gate][colpair][unit]
    float4 pwh3[3][15][30];     // packed-pair h-weights (L3)
    float2 xb [2][KS][32];
    float2 hb1[2][KS][32];
    float2 hb2[2][KS][32];
    float2 hb3[2][KS][32];
    float2 hb4[2][KS][32];
    float2 g1[3][KS][30];       // x-accum scratch (lane-private, guarded)
    float2 g2[3][KS][16];
    float2 g3[3][KS][30];
    float2 g4[3][KS][16];
    float  wtx1[3][32][30];     // x-side weights, transposed [gate][col][unit]
    float  wtx2[3][30][15];
    float  wtx3[3][15][30];
    float  wtx4[3][30][16];
};

static __device__ __forceinline__ float sigm(float x) {
    return __fdividef(1.0f, 1.0f + __expf(-x));
}
static __device__ __forceinline__ float tanh_f(float x) {
    float e = __expf(2.0f * x);
    return 1.0f - __fdividef(2.0f, e + 1.0f);
}

// Stage x-side weights transposed: dst[(g*IN + c)*HID + u] = wih[(g*HID+u)*IN + c]
template <int IN, int HID>
static __device__ void stage_x(float* dst, const float* __restrict__ wih, int tid) {
    for (int i = tid; i < 3 * IN * HID; i += NTHR) {
        int u = i % HID;
        int gc = i / HID;
        int c = gc % IN;
        int g = gc / IN;
        dst[(g * IN + c) * HID + u] = wih[(g * HID + u) * IN + c];
    }
}

// Stage packed-pair h-weights: dst[(g*NP+cp)*HID+u] = {w[u][2cp]x2, w[u][2cp+1]x2}
template <int HID, int NP>
static __device__ void stage_pwh(float4* dst, const float* __restrict__ whh, int tid) {
    for (int i = tid; i < 3 * NP * HID; i += NTHR) {
        int u  = i % HID;
        int cp = (i / HID) % NP;
        int g  = i / (HID * NP);
        float w0 = whh[(g * HID + u) * HID + 2 * cp];
        float w1 = whh[(g * HID + u) * HID + 2 * cp + 1];
        dst[i] = make_float4(w0, w0, w1, w1);
    }
}

// Shared x-phase: 8 independent steps, smem scalar weights packed per col,
// results into guarded lane-private scratch gx[3][KS][HID].
template <int IN, int HID>
static __device__ __forceinline__ void x_phase(
    const float* __restrict__ wtx, float2* gx,
    const float2* __restrict__ vb, int rp, int hc, bool active,
    u64 pbr, u64 pbz, u64 pbm)
{
    u64 axr[KS], axz[KS], axn[KS];
#pragma unroll
    for (int j = 0; j < KS; ++j) { axr[j] = pbr; axz[j] = pbz; axn[j] = pbm; }
#pragma unroll 4
    for (int c = 0; c < IN; ++c) {
        u64 wrp, wzp, wnp;
        float a = wtx[(0 * IN + c) * HID + hc];
        float b = wtx[(1 * IN + c) * HID + hc];
        float d = wtx[(2 * IN + c) * HID + hc];
        PACK2(wrp, a); PACK2(wzp, b); PACK2(wnp, d);
#pragma unroll
        for (int j = 0; j < KS; ++j) {
            u64 v2 = *(const u64*)(vb + (rp * KS + j) * 32 + c);   // broadcast
            FMA2(axr[j], wrp, v2);
            FMA2(axz[j], wzp, v2);
            FMA2(axn[j], wnp, v2);
        }
    }
    if (active) {
#pragma unroll
        for (int j = 0; j < KS; ++j) {
            *(u64*)(gx + (0 * KS + j) * HID + hc) = axr[j];
            *(u64*)(gx + (1 * KS + j) * HID + hc) = axz[j];
            *(u64*)(gx + (2 * KS + j) * HID + hc) = axn[j];
        }
    }
}

// Heavy layer (HID=30): packed-pair h-weights via direct longlong2 smem loads
// (value member access only — NO address-of-local).
template <int IN, int D>
static __device__ void layer_pwh(
    const float* __restrict__ wtx, const float4* __restrict__ pwh,
    float2* gx,
    const float* __restrict__ bih, const float* __restrict__ bhh,
    const float2* __restrict__ vb, float2* hb, int lane)
{
    const int HID = 30, NP = 15;
    const int hc = (lane < HID) ? lane : 0;
    const bool act_lane = (lane < HID);
    const float br = __ldg(bih + hc)           + __ldg(bhh + hc);
    const float bz = __ldg(bih + HID + hc)     + __ldg(bhh + HID + hc);
    const float bm = __ldg(bih + 2 * HID + hc);
    const float bn = __ldg(bhh + 2 * HID + hc);
    u64 pbr, pbz, pbm, pbn;
    PACK2(pbr, br); PACK2(pbz, bz); PACK2(pbm, bm); PACK2(pbn, bn);

    // Per-lane weight row bases (float4 elements are 16B => longlong2-aligned).
    const float4* pr = pwh + 0 * NP * HID + hc;
    const float4* pz = pwh + 1 * NP * HID + hc;
    const float4* pn = pwh + 2 * NP * HID + hc;

    float2 hp = {0.f, 0.f};

    for (int m = 0; m < NINT; ++m) {
        if (m >= D && m < D + T_LEN / KS) {
            const int wp = m & 1, rp = wp ^ 1;
            x_phase<IN, HID>(wtx, gx, vb, rp, hc, act_lane, pbr, pbz, pbm);
            // ---- h-phase: serial over the 8 steps (rolled) ----
#pragma unroll 1
            for (int j = 0; j < KS; ++j) {
                u64 ar = *(const u64*)(gx + (0 * KS + j) * HID + hc);
                u64 az = *(const u64*)(gx + (1 * KS + j) * HID + hc);
                u64 xm = *(const u64*)(gx + (2 * KS + j) * HID + hc);
                u64 an = pbn;
                const float2* hv = hb + ((j == 0) ? (rp * KS + KS - 1)
                                                  : (wp * KS + j - 1)) * 32;
#pragma unroll
                for (int cp = 0; cp < NP; ++cp) {
                    longlong2 hv2 = *(const longlong2*)(hv + 2 * cp);        // LDS.128
                    longlong2 w2r = *(const longlong2*)(pr + cp * HID);      // LDS.128
                    longlong2 w2z = *(const longlong2*)(pz + cp * HID);
                    longlong2 w2n = *(const longlong2*)(pn + cp * HID);
                    FMA2(ar, (u64)w2r.x, (u64)hv2.x); FMA2(ar, (u64)w2r.y, (u64)hv2.y);
                    FMA2(az, (u64)w2z.x, (u64)hv2.x); FMA2(az, (u64)w2z.y, (u64)hv2.y);
                    FMA2(an, (u64)w2n.x, (u64)hv2.x); FMA2(an, (u64)w2n.y, (u64)hv2.y);
                }
                float arx, ary, azx, azy, anx, any_, mx, my;
                UNPACK2(arx, ary, ar);
                UNPACK2(azx, azy, az);
                UNPACK2(anx, any_, an);
                UNPACK2(mx, my, xm);
                float rx = sigm(arx), ry = sigm(ary);
                float zx = sigm(azx), zy = sigm(azy);
                float nx = tanh_f(fmaf(rx, anx, mx));
                float ny = tanh_f(fmaf(ry, any_, my));
                float2 hn;
                hn.x = nx + zx * (hp.x - nx);
                hn.y = ny + zy * (hp.y - ny);
                hp = hn;
                if (act_lane) hb[(wp * KS + j) * 32 + lane] = hn;
                __syncwarp();
            }
        }
        BAR();
    }
}

// Light layer (HID<=16): register h-weights + PACK2V (R10 path, spill-safe).
template <int IN, int HID, int D>
static __device__ void layer_reg(
    const float* __restrict__ wtx, float2* gx,
    const float* __restrict__ whh,
    const float* __restrict__ bih, const float* __restrict__ bhh,
    const float2* __restrict__ vb, float2* hb, int lane)
{
    const int hc = (lane < HID) ? lane : 0;
    const bool act_lane = (lane < HID);
    float wr[HID], wz[HID], wn[HID];
#pragma unroll
    for (int c = 0; c < HID; ++c) {
        wr[c] = __ldg(whh + (0 * HID + hc) * HID + c);
        wz[c] = __ldg(whh + (1 * HID + hc) * HID + c);
        wn[c] = __ldg(whh + (2 * HID + hc) * HID + c);
    }
    const float br = __ldg(bih + hc)           + __ldg(bhh + hc);
    const float bz = __ldg(bih + HID + hc)     + __ldg(bhh + HID + hc);
    const float bm = __ldg(bih + 2 * HID + hc);
    const float bn = __ldg(bhh + 2 * HID + hc);
    u64 pbr, pbz, pbm;
    PACK2(pbr, br); PACK2(pbz, bz); PACK2(pbm, bm);

    float2 hp = {0.f, 0.f};

    for (int m = 0; m < NINT; ++m) {
        if (m >= D && m < D + T_LEN / KS) {
            const int wp = m & 1, rp = wp ^ 1;
            x_phase<IN, HID>(wtx, gx, vb, rp, hc, act_lane, pbr, pbz, pbm);
#pragma unroll 1
            for (int j = 0; j < KS; ++j) {
                u64 ar = *(const u64*)(gx + (0 * KS + j) * HID + hc);
                u64 az = *(const u64*)(gx + (1 * KS + j) * HID + hc);
                u64 xm = *(const u64*)(gx + (2 * KS + j) * HID + hc);
                u64 an; PACK2V(an, bn);
                const float2* hv = hb + ((j == 0) ? (rp * KS + KS - 1)
                                                  : (wp * KS + j - 1)) * 32;
#pragma unroll
                for (int c = 0; c < HID; ++c) {
                    u64 h2 = *(const u64*)(hv + c);
                    u64 t;
                    PACK2V(t, wr[c]); FMA2(ar, t, h2);
                    PACK2V(t, wz[c]); FMA2(az, t, h2);
                    PACK2V(t, wn[c]); FMA2(an, t, h2);
                }
                float arx, ary, azx, azy, anx, any_, mx, my;
                UNPACK2(arx, ary, ar);
                UNPACK2(azx, azy, az);
                UNPACK2(anx, any_, an);
                UNPACK2(mx, my, xm);
                float rx = sigm(arx), ry = sigm(ary);
                float zx = sigm(azx), zy = sigm(azy);
                float nx = tanh_f(fmaf(rx, anx, mx));
                float ny = tanh_f(fmaf(ry, any_, my));
                float2 hn;
                hn.x = nx + zx * (hp.x - nx);
                hn.y = ny + zy * (hp.y - ny);
                hp = hn;
                if (act_lane) hb[(wp * KS + j) * 32 + lane] = hn;
                __syncwarp();
            }
        }
        BAR();
    }
}

// FC warp: FC for group m-4 + x loader for group m+1 (R10 verbatim).
static __device__ void fc_warp(
    const float* __restrict__ fcw, const float* __restrict__ fcb,
    const float* __restrict__ x,   float* __restrict__ out,
    int bbase, int lane,
    const float2* __restrict__ hb4, float2* xb)
{
    const int c10 = (lane < 10) ? lane : 0;
    float w[16];
#pragma unroll
    for (int c = 0; c < 16; ++c) w[c] = __ldg(fcw + c10 * 16 + c);
    const float bfc = __ldg(fcb + c10);

    for (int m = 0; m < NINT; ++m) {
        const int wp = m & 1, rp = wp ^ 1;
#pragma unroll
        for (int j = 0; j < KS; ++j) {
            int s = KS * (m + 1) + j;
            if (s < T_LEN) {
                size_t off = (size_t)s * 32 + lane;
                float2 xv;
                xv.x = __ldg(x + (size_t)(bbase + 0) * T_LEN * 32 + off);
                xv.y = __ldg(x + (size_t)(bbase + 1) * T_LEN * 32 + off);
                xb[(wp * KS + j) * 32 + lane] = xv;
            }
        }
        if (m >= 4) {
#pragma unroll
            for (int j = 0; j < KS; ++j) {
                int t = KS * (m - 4) + j;
                const float2* h4 = hb4 + (rp * KS + j) * 32;
                float2 acc = make_float2(bfc, bfc);
#pragma unroll
                for (int c = 0; c < 16; ++c) {
                    float2 v = h4[c];
                    acc.x = fmaf(w[c], v.x, acc.x);
                    acc.y = fmaf(w[c], v.y, acc.y);
                }
                if (lane < 10) {
                    size_t base = ((size_t)bbase * 10 + lane) * T_LEN + t;
                    out[base]                      = acc.x;
                    out[base + 10 * (size_t)T_LEN] = acc.y;
                }
            }
        }
        BAR();
    }
}

__global__ void __launch_bounds__(NTHR, 2)
gru_ae_k8e_kernel(const float* __restrict__ x,
                  const float* __restrict__ fcw,  const float* __restrict__ fcb,
                  const float* __restrict__ wih1, const float* __restrict__ whh1,
                  const float* __restrict__ bih1, const float* __restrict__ bhh1,
                  const float* __restrict__ wih2, const float* __restrict__ whh2,
                  const float* __restrict__ bih2, const float* __restrict__ bhh2,
                  const float* __restrict__ wih3, const float* __restrict__ whh3,
                  const float* __restrict__ bih3, const float* __restrict__ bhh3,
                  const float* __restrict__ wih4, const float* __restrict__ whh4,
                  const float* __restrict__ bih4, const float* __restrict__ bhh4,
                  float* __restrict__ out)
{
    extern __shared__ char raw[];
    Smem* sm = (Smem*)raw;

    const int tid   = threadIdx.x;
    const int wid   = tid >> 5;
    const int lane  = tid & 31;
    const int bbase = blockIdx.x * 2;
    const bool odd  = (blockIdx.x & 1) != 0;

    stage_x<32, 30>(&sm->wtx1[0][0][0], wih1, tid);
    stage_x<30, 15>(&sm->wtx2[0][0][0], wih2, tid);
    stage_x<15, 30>(&sm->wtx3[0][0][0], wih3, tid);
    stage_x<30, 16>(&sm->wtx4[0][0][0], wih4, tid);
    stage_pwh<30, 15>(&sm->pwh1[0][0][0], whh1, tid);
    stage_pwh<30, 15>(&sm->pwh3[0][0][0], whh3, tid);
    {
        float2 z2 = {0.f, 0.f};
        float2* zb = &sm->xb[0][0][0];     // xb + hb1..hb4 contiguous
        for (int i = tid; i < 5 * 2 * KS * 32; i += NTHR) zb[i] = z2;
    }
    __syncthreads();

    // Prelude: x group 0 into xb slot 1 (L1 at m=0 reads parity 1).
    if (wid == 0) {
#pragma unroll
        for (int j = 0; j < KS; ++j) {
            size_t off = (size_t)j * 32 + lane;
            float2 xv;
            xv.x = __ldg(x + (size_t)(bbase + 0) * T_LEN * 32 + off);
            xv.y = __ldg(x + (size_t)(bbase + 1) * T_LEN * 32 + off);
            sm->xb[1][j][lane] = xv;
        }
    }
    __syncthreads();

    // Parity-staggered layer->warp map (SMSP = wid%4), as R10:
    //  even block: wid0=L2 wid1=L1 wid2=L3 wid3=L4 wid4=FC
    //  odd  block: wid0=L4 wid1=L3 wid2=L2 wid3=L1 wid4=FC
    if (wid == 4) {
        fc_warp(fcw, fcb, x, out, bbase, lane,
                &sm->hb4[0][0][0], &sm->xb[0][0][0]);
    } else if ((!odd && wid == 1) || (odd && wid == 3)) {
        layer_pwh<32, 0>(&sm->wtx1[0][0][0], &sm->pwh1[0][0][0],
                         &sm->g1[0][0][0], bih1, bhh1,
                         &sm->xb[0][0][0], &sm->hb1[0][0][0], lane);
    } else if ((!odd && wid == 0) || (odd && wid == 2)) {
        layer_reg<30, 15, 1>(&sm->wtx2[0][0][0], &sm->g2[0][0][0], whh2,
                             bih2, bhh2,
                             &sm->hb1[0][0][0], &sm->hb2[0][0][0], lane);
    } else if ((!odd && wid == 2) || (odd && wid == 1)) {
        layer_pwh<15, 2>(&sm->wtx3[0][0][0], &sm->pwh3[0][0][0],
                         &sm->g3[0][0][0], bih3, bhh3,
                         &sm->hb2[0][0][0], &sm->hb3[0][0][0], lane);
    } else {
        layer_reg<30, 16, 3>(&sm->wtx4[0][0][0], &sm->g4[0][0][0], whh4,
                             bih4, bhh4,
                             &sm->hb3[0][0][0], &sm->hb4[0][0][0], lane);
    }
}

extern "C" void kernel_launch(void* const* d_in, const int* in_sizes, int n_in,
                              void* d_out, int out_size) {
    (void)in_sizes; (void)n_in; (void)out_size;
    const float* x    = (const float*)d_in[0];
    const float* fcw  = (const float*)d_in[1];
    const float* fcb  = (const float*)d_in[2];
    const float* wih1 = (const float*)d_in[3];
    const float* whh1 = (const float*)d_in[4];
    const float* bih1 = (const float*)d_in[5];
    const float* bhh1 = (const float*)d_in[6];
    const float* wih2 = (const float*)d_in[7];
    const float* whh2 = (const float*)d_in[8];
    const float* bih2 = (const float*)d_in[9];
    const float* bhh2 = (const float*)d_in[10];
    const float* wih3 = (const float*)d_in[11];
    const float* whh3 = (const float*)d_in[12];
    const float* bih3 = (const float*)d_in[13];
    const float* bhh3 = (const float*)d_in[14];
    const float* wih4 = (const float*)d_in[15];
    const float* whh4 = (const float*)d_in[16];
    const float* bih4 = (const float*)d_in[17];
    const float* bhh4 = (const float*)d_in[18];
    float* out = (float*)d_out;

    cudaFuncSetAttribute(gru_ae_k8e_kernel,
                         cudaFuncAttributeMaxDynamicSharedMemorySize,
                         (int)sizeof(Smem));

    gru_ae_k8e_kernel<<<NBLK, NTHR, sizeof(Smem)>>>(
        x, fcw, fcb,
        wih1, whh1, bih1, bhh1,
        wih2, whh2, bih2, bhh2,
        wih3, whh3, bih3, bhh3,
        wih4, whh4, bih4, bhh4,
        out);
}